// round 1
// baseline (speedup 1.0000x reference)
#include <cuda_runtime.h>
#include <cstdint>

#define EDIM 256
#define NE 1024
#define HW 4096
#define N_TOK 65536
#define ZQ_ELEMS 16777216
#define OFF_LOSS 16777216
#define OFF_ZERO 16777217
#define OFF_IDX  16777218

typedef unsigned long long ull;

__device__ int   g_idx[N_TOK];
__device__ float g_cnorm[NE];
__device__ float g_part[16384];

__device__ __forceinline__ ull pk(float a, float b){
    ull r; asm("mov.b64 %0, {%1,%2};" : "=l"(r) : "f"(a), "f"(b)); return r;
}
__device__ __forceinline__ void fma2(ull& d, ull a, ull b){
    asm("fma.rn.f32x2 %0, %1, %2, %0;" : "+l"(d) : "l"(a), "l"(b));
}
__device__ __forceinline__ void unpk(ull v, float& a, float& b){
    asm("mov.b64 {%0,%1}, %2;" : "=f"(a), "=f"(b) : "l"(v));
}
// monotone float->uint map: order-preserving for all finite floats
__device__ __forceinline__ unsigned fenc(float x){
    unsigned u = __float_as_uint(x);
    return (u & 0x80000000u) ? ~u : (u | 0x80000000u);
}

// -------------------- kernel 1: codebook squared norms --------------------
__global__ void cnorm_kernel(const float* __restrict__ cb){
    __shared__ float red[256];
    int tid = threadIdx.x;
    float v = cb[blockIdx.x * EDIM + tid];
    red[tid] = v * v;
    __syncthreads();
    for (int s = 128; s > 0; s >>= 1){
        if (tid < s) red[tid] += red[tid + s];
        __syncthreads();
    }
    if (tid == 0) g_cnorm[blockIdx.x] = red[0];
}

// -------------------- kernel 2: fused distance GEMM + argmin --------------------
// Block: 64 tokens x all 1024 codes. 256 threads, each 8 tokens x 8 codes.
// score = ||c||^2 - 2*dot(z,c)  (||z||^2 constant per token -> argmin-invariant)
// Accumulators packed over token pairs using fma.rn.f32x2 (double-rate fp32).
__global__ __launch_bounds__(256, 2)
void vq_argmin_kernel(const float* __restrict__ z, const float* __restrict__ cb,
                      float* __restrict__ out){
    extern __shared__ char smem_raw[];
    float* zs  = (float*)smem_raw;                      // [256][64]
    float* cs  = (float*)(smem_raw + 65536);            // [16][256]
    ull*   keys = (ull*)(smem_raw + 65536 + 16384);     // [64]

    const int tid = threadIdx.x;
    const int n0  = blockIdx.x << 6;        // first token of this block
    const int b   = n0 >> 12;               // batch (4096 tokens per batch, tiles never cross)
    const int hw0 = n0 & 4095;
    const float* zbase = z + (size_t)b * (EDIM * HW) + hw0;

    // Load z tile [256 k][64 tok], coalesced float4 over tokens
    for (int i = tid; i < 4096; i += 256){
        int k  = i >> 4;
        int t4 = (i & 15) << 2;
        float4 v = *(const float4*)(zbase + (size_t)k * HW + t4);
        *(float4*)(zs + k * 64 + t4) = v;
    }
    if (tid < 64) keys[tid] = ~0ULL;

    const int tt   = tid & 7;        // token group: tokens tt*8 .. tt*8+7
    const int tc   = tid >> 3;       // code group : codes  tc*8 .. tc*8+7 (within 256-code tile)
    const int tok0 = tt << 3;

    ull best[8];
    #pragma unroll
    for (int i = 0; i < 8; i++) best[i] = ~0ULL;

    __syncthreads();

    for (int tile = 0; tile < 4; tile++){
        const int cbase = tile << 8;

        ull acc[4][8];
        #pragma unroll
        for (int tp = 0; tp < 4; tp++)
            #pragma unroll
            for (int j = 0; j < 8; j++) acc[tp][j] = 0ULL;

        for (int ch = 0; ch < 16; ch++){
            // prefetch this thread's code row slice (code = cbase+tid, 16 k values)
            const float* crow = cb + (size_t)(cbase + tid) * EDIM + (ch << 4);
            float4 v0 = __ldg((const float4*)(crow));
            float4 v1 = __ldg((const float4*)(crow + 4));
            float4 v2 = __ldg((const float4*)(crow + 8));
            float4 v3 = __ldg((const float4*)(crow + 12));
            __syncthreads();   // previous chunk's compute done before overwrite
            // transpose-store: cs[k][code] — each STS: 32 lanes, consecutive codes -> conflict-free
            cs[ 0*256 + tid] = v0.x; cs[ 1*256 + tid] = v0.y;
            cs[ 2*256 + tid] = v0.z; cs[ 3*256 + tid] = v0.w;
            cs[ 4*256 + tid] = v1.x; cs[ 5*256 + tid] = v1.y;
            cs[ 6*256 + tid] = v1.z; cs[ 7*256 + tid] = v1.w;
            cs[ 8*256 + tid] = v2.x; cs[ 9*256 + tid] = v2.y;
            cs[10*256 + tid] = v2.z; cs[11*256 + tid] = v2.w;
            cs[12*256 + tid] = v3.x; cs[13*256 + tid] = v3.y;
            cs[14*256 + tid] = v3.z; cs[15*256 + tid] = v3.w;
            __syncthreads();

            #pragma unroll
            for (int k = 0; k < 16; k++){
                const float* zr = zs + ((ch << 4) + k) * 64 + tok0;
                float4 za = *(const float4*)zr;
                float4 zb2 = *(const float4*)(zr + 4);
                ull zp0 = pk(za.x,  za.y),  zp1 = pk(za.z,  za.w);
                ull zp2 = pk(zb2.x, zb2.y), zp3 = pk(zb2.z, zb2.w);

                const float* cr = cs + k * 256 + (tc << 3);
                float4 ca  = *(const float4*)cr;
                float4 cb4 = *(const float4*)(cr + 4);
                ull c0 = pk(ca.x,  ca.x),  c1 = pk(ca.y,  ca.y);
                ull c2 = pk(ca.z,  ca.z),  c3 = pk(ca.w,  ca.w);
                ull c4 = pk(cb4.x, cb4.x), c5 = pk(cb4.y, cb4.y);
                ull c6 = pk(cb4.z, cb4.z), c7 = pk(cb4.w, cb4.w);

                fma2(acc[0][0], zp0, c0); fma2(acc[1][0], zp1, c0);
                fma2(acc[2][0], zp2, c0); fma2(acc[3][0], zp3, c0);
                fma2(acc[0][1], zp0, c1); fma2(acc[1][1], zp1, c1);
                fma2(acc[2][1], zp2, c1); fma2(acc[3][1], zp3, c1);
                fma2(acc[0][2], zp0, c2); fma2(acc[1][2], zp1, c2);
                fma2(acc[2][2], zp2, c2); fma2(acc[3][2], zp3, c2);
                fma2(acc[0][3], zp0, c3); fma2(acc[1][3], zp1, c3);
                fma2(acc[2][3], zp2, c3); fma2(acc[3][3], zp3, c3);
                fma2(acc[0][4], zp0, c4); fma2(acc[1][4], zp1, c4);
                fma2(acc[2][4], zp2, c4); fma2(acc[3][4], zp3, c4);
                fma2(acc[0][5], zp0, c5); fma2(acc[1][5], zp1, c5);
                fma2(acc[2][5], zp2, c5); fma2(acc[3][5], zp3, c5);
                fma2(acc[0][6], zp0, c6); fma2(acc[1][6], zp1, c6);
                fma2(acc[2][6], zp2, c6); fma2(acc[3][6], zp3, c6);
                fma2(acc[0][7], zp0, c7); fma2(acc[1][7], zp1, c7);
                fma2(acc[2][7], zp2, c7); fma2(acc[3][7], zp3, c7);
            }
        }

        // fold this 256-code tile into per-thread best keys
        #pragma unroll
        for (int j = 0; j < 8; j++){
            int code = cbase + (tc << 3) + j;
            float cn = g_cnorm[code];
            #pragma unroll
            for (int tp = 0; tp < 4; tp++){
                float d0, d1;
                unpk(acc[tp][j], d0, d1);
                float dist0 = cn - 2.0f * d0;
                float dist1 = cn - 2.0f * d1;
                ull k0 = ((ull)fenc(dist0) << 32) | (unsigned)code;
                ull k1 = ((ull)fenc(dist1) << 32) | (unsigned)code;
                if (k0 < best[2*tp])     best[2*tp]     = k0;
                if (k1 < best[2*tp + 1]) best[2*tp + 1] = k1;
            }
        }
    }

    // cross-thread reduction: 32 code-groups per token -> smem atomicMin (deterministic key)
    #pragma unroll
    for (int i = 0; i < 8; i++) atomicMin(&keys[tok0 + i], best[i]);
    __syncthreads();

    if (tid < 64){
        int idx = (int)(unsigned)(keys[tid] & 0xFFFFFFFFULL);
        g_idx[n0 + tid] = idx;
        out[OFF_IDX + n0 + tid] = (float)idx;   // indices output (B,1,H,W), cast to f32
    }
}

// -------------------- kernel 3: gather z_q (B,C,H,W) + loss partials --------------------
__global__ void gather_kernel(const float* __restrict__ z, const float* __restrict__ cb,
                              float* __restrict__ out){
    __shared__ float red[8];
    int t  = blockIdx.x * 256 + threadIdx.x;
    int o4 = t << 2;                          // linear index into (B,C,H,W), float4
    int b   = o4 >> 20;                       // 256*4096 = 2^20 elems per batch
    int rem = o4 & 1048575;
    int c   = rem >> 12;
    int hw  = rem & 4095;
    int n   = (b << 12) + hw;

    float4 zv = *(const float4*)(z + o4);
    int i0 = g_idx[n], i1 = g_idx[n+1], i2 = g_idx[n+2], i3 = g_idx[n+3];
    float4 q;
    q.x = __ldg(cb + (size_t)i0 * EDIM + c);
    q.y = __ldg(cb + (size_t)i1 * EDIM + c);
    q.z = __ldg(cb + (size_t)i2 * EDIM + c);
    q.w = __ldg(cb + (size_t)i3 * EDIM + c);
    *(float4*)(out + o4) = q;

    float dx = q.x - zv.x, dy = q.y - zv.y, dz = q.z - zv.z, dw = q.w - zv.w;
    float s = dx*dx + dy*dy + dz*dz + dw*dw;

    #pragma unroll
    for (int off = 16; off; off >>= 1) s += __shfl_down_sync(0xffffffffu, s, off);
    int lane = threadIdx.x & 31, wid = threadIdx.x >> 5;
    if (lane == 0) red[wid] = s;
    __syncthreads();
    if (wid == 0){
        float v = (lane < 8) ? red[lane] : 0.0f;
        #pragma unroll
        for (int off = 4; off; off >>= 1) v += __shfl_down_sync(0xffffffffu, v, off);
        if (lane == 0) g_part[blockIdx.x] = v;   // deterministic per-block partial
    }
}

// -------------------- kernel 4: deterministic final loss reduction --------------------
__global__ void finalize_kernel(float* __restrict__ out){
    __shared__ float red[256];
    int tid = threadIdx.x;
    float s = 0.0f;
    for (int j = 0; j < 64; j++) s += g_part[tid + (j << 8)];  // fixed order
    red[tid] = s;
    __syncthreads();
    for (int st = 128; st > 0; st >>= 1){
        if (tid < st) red[tid] += red[tid + st];
        __syncthreads();
    }
    if (tid == 0){
        out[OFF_LOSS] = red[0] / 16777216.0f;
        out[OFF_ZERO] = 0.0f;
    }
}

// -------------------- launch --------------------
extern "C" void kernel_launch(void* const* d_in, const int* in_sizes, int n_in,
                              void* d_out, int out_size){
    const float* z  = (const float*)d_in[0];
    const float* cb = (const float*)d_in[1];
    if (n_in >= 2 && in_sizes[0] == NE * EDIM && in_sizes[1] == ZQ_ELEMS){
        const float* t = z; z = cb; cb = t;   // defensive: swap if order reversed
    }
    float* out = (float*)d_out;

    const int SMEM = 65536 + 16384 + 512;     // zs + cs + keys = 82432 B
    cudaFuncSetAttribute(vq_argmin_kernel,
                         cudaFuncAttributeMaxDynamicSharedMemorySize, SMEM);

    cnorm_kernel<<<NE, 256>>>(cb);
    vq_argmin_kernel<<<N_TOK / 64, 256, SMEM>>>(z, cb, out);
    gather_kernel<<<ZQ_ELEMS / 1024, 256>>>(z, cb, out);
    finalize_kernel<<<1, 256>>>(out);
}